// round 15
// baseline (speedup 1.0000x reference)
#include <cuda_runtime.h>
#include <cuda_bf16.h>
#include <cstdint>

#define MARGIN 1.0f
#define NBLK   296          // 148 SMs * 2 CTAs -> one wave
#define NTHR   256
#define NWARP  (NTHR / 32)
#define NQ     5            // a, sz, sz2, S, S2
#define PIPE   4            // label ring stages
#define STG_I  4096         // ints per stage (16KB labels; preds via LDG)
#define F4_PER_STG (STG_I / 4)          // 1024 float4 / int4
#define F4_PER_THR (F4_PER_STG / NTHR)  // 4

// Per-block partials, [quantity][block]. __device__ globals => no allocation.
__device__ float        g_part[NQ * NBLK];
__device__ unsigned int g_count = 0;

__device__ __forceinline__ uint32_t smem_u32(const void* p) {
    uint32_t a;
    asm("{ .reg .u64 t; cvta.to.shared.u64 t, %1; cvt.u32.u64 %0, t; }"
        : "=r"(a) : "l"(p));
    return a;
}
__device__ __forceinline__ void mbar_init(uint32_t mbar, uint32_t cnt) {
    asm volatile("mbarrier.init.shared.b64 [%0], %1;" :: "r"(mbar), "r"(cnt) : "memory");
}
__device__ __forceinline__ void mbar_expect_tx(uint32_t mbar, uint32_t bytes) {
    asm volatile("mbarrier.arrive.expect_tx.shared.b64 _, [%0], %1;"
                 :: "r"(mbar), "r"(bytes) : "memory");
}
__device__ __forceinline__ void mbar_arrive(uint32_t mbar) {
    asm volatile("mbarrier.arrive.shared.b64 _, [%0];" :: "r"(mbar) : "memory");
}
__device__ __forceinline__ void mbar_wait(uint32_t mbar, uint32_t parity) {
    asm volatile(
        "{\n\t"
        ".reg .pred P;\n\t"
        "WL_%=:\n\t"
        "mbarrier.try_wait.parity.acquire.cta.shared::cta.b64 P, [%0], %1, 0x989680;\n\t"
        "@P bra.uni WD_%=;\n\t"
        "bra.uni WL_%=;\n\t"
        "WD_%=:\n\t"
        "}" :: "r"(mbar), "r"(parity) : "memory");
}
__device__ __forceinline__ void mbar_wait_relaxed(uint32_t mbar, uint32_t parity) {
    asm volatile(
        "{\n\t"
        ".reg .pred P;\n\t"
        "WL_%=:\n\t"
        "mbarrier.try_wait.parity.relaxed.cta.shared::cta.b64 P, [%0], %1, 0x989680;\n\t"
        "@P bra.uni WD_%=;\n\t"
        "bra.uni WL_%=;\n\t"
        "WD_%=:\n\t"
        "}" :: "r"(mbar), "r"(parity) : "memory");
}
__device__ __forceinline__ void bulk_ld(uint32_t dst, const void* src,
                                        uint32_t bytes, uint32_t mbar) {
    asm volatile(
        "cp.async.bulk.shared::cluster.global.mbarrier::complete_tx::bytes "
        "[%0], [%1], %2, [%3];"
        :: "r"(dst), "l"(src), "r"(bytes), "r"(mbar) : "memory");
}

__device__ __forceinline__ float warp_sum(float v) {
    #pragma unroll
    for (int o = 16; o > 0; o >>= 1) v += __shfl_xor_sync(0xFFFFFFFFu, v, o);
    return v;
}
__device__ __forceinline__ double warp_sum_d(double v) {
    #pragma unroll
    for (int o = 16; o > 0; o >>= 1) v += __shfl_xor_sync(0xFFFFFFFFu, v, o);
    return v;
}

// Per-element update: unmasked S, S2; masked a, sz, sz2 (positives only).
__device__ __forceinline__ void acc1(float pv, int lv,
                                     float& a, float& sz, float& sz2,
                                     float& S, float& S2)
{
    S  += pv;
    S2  = fmaf(pv, pv, S2);
    float m = (lv == 1) ? 1.f : 0.f;
    float z = m * (MARGIN - pv);
    a  += m;
    sz += z;
    sz2 = fmaf(z, z, sz2);
}

__global__ __launch_bounds__(NTHR, 2) void sqloss_hybrid(
    const float* __restrict__ pred, const int* __restrict__ lab, int n,
    float* __restrict__ out)
{
    __shared__ __align__(128) int s_lab[PIPE][STG_I];     // 64KB label ring
    __shared__ __align__(8) uint64_t s_full [PIPE];
    __shared__ __align__(8) uint64_t s_empty[PIPE];

    const int tid  = threadIdx.x;
    const int lane = tid & 31;
    const int wid  = tid >> 5;

    uint32_t fullb [PIPE];
    uint32_t emptyb[PIPE];
    #pragma unroll
    for (int s = 0; s < PIPE; s++) {
        fullb [s] = smem_u32(&s_full [s]);
        emptyb[s] = smem_u32(&s_empty[s]);
    }

    if (tid == 0) {
        #pragma unroll
        for (int s = 0; s < PIPE; s++) {
            mbar_init(fullb [s], 1);      // completed by TMA tx bytes
            mbar_init(emptyb[s], NWARP);  // one arrive per warp
        }
    }
    __syncthreads();

    // ── contiguous stage range for this CTA ──
    const int nStage = n / STG_I;
    const int base   = nStage / NBLK;
    const int rem    = nStage - base * NBLK;
    const int cnt    = base + (blockIdx.x < rem ? 1 : 0);
    const int st0    = blockIdx.x * base + min((int)blockIdx.x, rem);

    // ── producer prologue: fill the label ring ──
    if (tid == 0) {
        const int pre = cnt < PIPE ? cnt : PIPE;
        for (int k = 0; k < pre; k++) {
            mbar_expect_tx(fullb[k], STG_I * 4);
            bulk_ld(smem_u32(&s_lab[k][0]), lab + (size_t)(st0 + k) * STG_I,
                    STG_I * 4, fullb[k]);
        }
    }

    float a = 0.f, sz = 0.f, sz2 = 0.f, S = 0.f, S2 = 0.f;

    const float4* __restrict__ p4 = reinterpret_cast<const float4*>(pred);

    // ── hybrid consume loop: LDG preds overlap the TMA label wait ──
    int slot = 0, phase = 0;
    for (int i = 0; i < cnt; i++) {
        const size_t sbase = (size_t)(st0 + i) * F4_PER_STG;

        // issue the 4 pred LDG.128 BEFORE waiting on the label barrier
        float4 pf[F4_PER_THR];
        #pragma unroll
        for (int k = 0; k < F4_PER_THR; k++)
            pf[k] = __ldcs(&p4[sbase + k * NTHR + tid]);

        mbar_wait(fullb[slot], phase);

        const int4* sl = reinterpret_cast<const int4*>(&s_lab[slot][0]);
        #pragma unroll
        for (int k = 0; k < F4_PER_THR; k++) {
            int4 lv = sl[k * NTHR + tid];
            acc1(pf[k].x, lv.x, a, sz, sz2, S, S2);
            acc1(pf[k].y, lv.y, a, sz, sz2, S, S2);
            acc1(pf[k].z, lv.z, a, sz, sz2, S, S2);
            acc1(pf[k].w, lv.w, a, sz, sz2, S, S2);
        }

        __syncwarp();
        if (lane == 0) mbar_arrive(emptyb[slot]);

        if (tid == 0) {
            int j = i + PIPE;
            if (j < cnt) {
                mbar_wait_relaxed(emptyb[slot], phase);   // all warps done
                mbar_expect_tx(fullb[slot], STG_I * 4);
                bulk_ld(smem_u32(&s_lab[slot][0]),
                        lab + (size_t)(st0 + j) * STG_I, STG_I * 4, fullb[slot]);
            }
        }
        if (++slot == PIPE) { slot = 0; phase ^= 1; }
    }

    // scalar tail (n not multiple of STG_I) — global thread 0 only
    if (blockIdx.x == 0 && tid == 0) {
        for (int j = nStage * STG_I; j < n; j++)
            acc1(pred[j], lab[j], a, sz, sz2, S, S2);
    }

    // ── block reduction ──
    __shared__ float sm[NQ][NWARP];
    float vals[NQ] = {a, sz, sz2, S, S2};

    #pragma unroll
    for (int j = 0; j < NQ; j++) {
        float v = warp_sum(vals[j]);
        if (lane == 0) sm[j][wid] = v;
    }
    __syncthreads();

    if (wid == 0) {
        #pragma unroll
        for (int j = 0; j < NQ; j++) {
            float v = (lane < NWARP) ? sm[j][lane] : 0.f;
            v = warp_sum(v);
            if (lane == 0) g_part[j * NBLK + blockIdx.x] = v;
        }
    }

    // ── last-block-done finalize ──
    __shared__ bool amLast;
    __threadfence();
    if (tid == 0) {
        unsigned int t = atomicAdd(&g_count, 1u);
        amLast = (t == gridDim.x - 1);
    }
    __syncthreads();

    if (amLast) {
        __shared__ double smd[NQ][NWARP];
        double acc[NQ];
        #pragma unroll
        for (int j = 0; j < NQ; j++) {
            double v = 0.0;
            for (int b = tid; b < NBLK; b += NTHR)
                v += (double)g_part[j * NBLK + b];
            v = warp_sum_d(v);
            if (lane == 0) smd[j][wid] = v;
        }
        __syncthreads();
        if (wid == 0) {
            #pragma unroll
            for (int j = 0; j < NQ; j++) {
                double v = (lane < NWARP) ? smd[j][lane] : 0.0;
                acc[j] = warp_sum_d(v);
            }
            if (lane == 0) {
                double A   = acc[0];
                double SZ  = acc[1];
                double SZ2 = acc[2];
                double Sd  = acc[3];
                double S2d = acc[4];
                double NN  = (double)n - A;                // n_neg
                double SP  = Sd  - (A - SZ);               // sum_neg p
                double SP2 = S2d - (A - 2.0 * SZ + SZ2);   // sum_neg p^2
                out[0] = (float)(A * SP2 + 2.0 * SZ * SP + SZ2 * NN);
                g_count = 0;   // reset for next graph replay
            }
        }
    }
}

extern "C" void kernel_launch(void* const* d_in, const int* in_sizes, int n_in,
                              void* d_out, int out_size)
{
    const float* pred = (const float*)d_in[0];
    const int*   lab  = (const int*)d_in[1];
    float*       out  = (float*)d_out;
    const int n = in_sizes[0];

    sqloss_hybrid<<<NBLK, NTHR>>>(pred, lab, n, out);
}

// round 16
// speedup vs baseline: 1.1385x; 1.1385x over previous
#include <cuda_runtime.h>
#include <cuda_bf16.h>
#include <cstdint>

#define MARGIN 1.0f
#define NBLK  592           // 148 SMs * 4 CTAs -> one balanced wave
#define NTHR  256
#define NWARP (NTHR / 32)
#define NQ    5             // a, sz, sz2, S, S2
#define CH    1024          // float4 per chunk: 16KB pred + 16KB lab
#define PD    4             // prefetch distance (chunks ahead)

// Per-block partials, [quantity][block]. __device__ globals => no allocation.
__device__ float        g_part[NQ * NBLK];
__device__ unsigned int g_count = 0;

__device__ __forceinline__ void prefetch_l2(const void* p, uint32_t bytes) {
    asm volatile("cp.async.bulk.prefetch.L2.global [%0], %1;"
                 :: "l"(p), "r"(bytes) : "memory");
}

__device__ __forceinline__ float warp_sum(float v) {
    #pragma unroll
    for (int o = 16; o > 0; o >>= 1) v += __shfl_xor_sync(0xFFFFFFFFu, v, o);
    return v;
}
__device__ __forceinline__ double warp_sum_d(double v) {
    #pragma unroll
    for (int o = 16; o > 0; o >>= 1) v += __shfl_xor_sync(0xFFFFFFFFu, v, o);
    return v;
}

// Per-element update: unmasked S, S2; masked a, sz, sz2 (positives only).
__device__ __forceinline__ void acc1(float pv, int lv,
                                     float& a, float& sz, float& sz2,
                                     float& S, float& S2)
{
    S  += pv;
    S2  = fmaf(pv, pv, S2);
    float m = (lv == 1) ? 1.f : 0.f;
    float z = m * (MARGIN - pv);
    a  += m;
    sz += z;
    sz2 = fmaf(z, z, sz2);
}

__device__ __forceinline__ void acc4(const float4& pv, const int4& lv,
                                     float& a, float& sz, float& sz2,
                                     float& S, float& S2)
{
    acc1(pv.x, lv.x, a, sz, sz2, S, S2);
    acc1(pv.y, lv.y, a, sz, sz2, S, S2);
    acc1(pv.z, lv.z, a, sz, sz2, S, S2);
    acc1(pv.w, lv.w, a, sz, sz2, S, S2);
}

// 4 CTAs/SM cap -> 64-register budget -> 8 front-batched LDG.128 fit.
__global__ __launch_bounds__(NTHR, 4) void sqloss_pf(
    const float* __restrict__ pred, const int* __restrict__ lab, int n,
    float* __restrict__ out)
{
    const float4* __restrict__ p4 = reinterpret_cast<const float4*>(pred);
    const int4*   __restrict__ l4 = reinterpret_cast<const int4*>(lab);
    const int n4 = n >> 2;

    const int tid  = threadIdx.x;
    const int lane = tid & 31;
    const int wid  = tid >> 5;

    // ── contiguous chunk range for this CTA ──
    const int nChunk = n4 / CH;
    const int base   = nChunk / NBLK;
    const int rem    = nChunk - base * NBLK;
    const int cnt    = base + (blockIdx.x < rem ? 1 : 0);
    const int c0     = blockIdx.x * base + min((int)blockIdx.x, rem);

    // ── prologue prefetch: first PD chunks of this CTA's slab ──
    if (tid == 0) {
        const int pre = cnt < PD ? cnt : PD;
        for (int k = 0; k < pre; k++) {
            const size_t b = (size_t)(c0 + k) * CH;
            prefetch_l2(p4 + b, CH * 16);
            prefetch_l2(l4 + b, CH * 16);
        }
    }

    float a = 0.f, sz = 0.f, sz2 = 0.f, S = 0.f, S2 = 0.f;

    // ── chunk loop: prefetch chunk i+PD, consume chunk i from (mostly) L2 ──
    for (int i = 0; i < cnt; i++) {
        if (tid == 0 && i + PD < cnt) {
            const size_t b = (size_t)(c0 + i + PD) * CH;
            prefetch_l2(p4 + b, CH * 16);
            prefetch_l2(l4 + b, CH * 16);
        }

        const size_t b = (size_t)(c0 + i) * CH + tid;
        // 8 front-batched 128-bit loads (CH/NTHR = 4 float4 per thread)
        float4 p0 = __ldcs(&p4[b]);
        float4 p1 = __ldcs(&p4[b + NTHR]);
        float4 p2 = __ldcs(&p4[b + 2 * NTHR]);
        float4 p3 = __ldcs(&p4[b + 3 * NTHR]);
        int4   l0 = __ldcs(&l4[b]);
        int4   l1 = __ldcs(&l4[b + NTHR]);
        int4   l2 = __ldcs(&l4[b + 2 * NTHR]);
        int4   l3 = __ldcs(&l4[b + 3 * NTHR]);

        acc4(p0, l0, a, sz, sz2, S, S2);
        acc4(p1, l1, a, sz, sz2, S, S2);
        acc4(p2, l2, a, sz, sz2, S, S2);
        acc4(p3, l3, a, sz, sz2, S, S2);
    }

    // vector remainder (n4 not multiple of CH) — grid-linear
    {
        const int gtid = blockIdx.x * NTHR + tid;
        for (int i = nChunk * CH + gtid; i < n4; i += NBLK * NTHR) {
            float4 pv = __ldcs(&p4[i]);
            int4   lv = __ldcs(&l4[i]);
            acc4(pv, lv, a, sz, sz2, S, S2);
        }
    }

    // scalar tail (n not multiple of 4) — global thread 0 only
    if (blockIdx.x == 0 && tid == 0) {
        for (int j = n4 << 2; j < n; j++)
            acc1(pred[j], lab[j], a, sz, sz2, S, S2);
    }

    // ── block reduction ──
    __shared__ float sm[NQ][NWARP];
    float vals[NQ] = {a, sz, sz2, S, S2};

    #pragma unroll
    for (int j = 0; j < NQ; j++) {
        float v = warp_sum(vals[j]);
        if (lane == 0) sm[j][wid] = v;
    }
    __syncthreads();

    if (wid == 0) {
        #pragma unroll
        for (int j = 0; j < NQ; j++) {
            float v = (lane < NWARP) ? sm[j][lane] : 0.f;
            v = warp_sum(v);
            if (lane == 0) g_part[j * NBLK + blockIdx.x] = v;
        }
    }

    // ── last-block-done finalize ──
    __shared__ bool amLast;
    __threadfence();
    if (tid == 0) {
        unsigned int t = atomicAdd(&g_count, 1u);
        amLast = (t == gridDim.x - 1);
    }
    __syncthreads();

    if (amLast) {
        __shared__ double smd[NQ][NWARP];
        double acc[NQ];
        #pragma unroll
        for (int j = 0; j < NQ; j++) {
            double v = 0.0;
            for (int b = tid; b < NBLK; b += NTHR)
                v += (double)g_part[j * NBLK + b];
            v = warp_sum_d(v);
            if (lane == 0) smd[j][wid] = v;
        }
        __syncthreads();
        if (wid == 0) {
            #pragma unroll
            for (int j = 0; j < NQ; j++) {
                double v = (lane < NWARP) ? smd[j][lane] : 0.0;
                acc[j] = warp_sum_d(v);
            }
            if (lane == 0) {
                double A   = acc[0];
                double SZ  = acc[1];
                double SZ2 = acc[2];
                double Sd  = acc[3];
                double S2d = acc[4];
                double NN  = (double)n - A;                // n_neg
                double SP  = Sd  - (A - SZ);               // sum_neg p
                double SP2 = S2d - (A - 2.0 * SZ + SZ2);   // sum_neg p^2
                out[0] = (float)(A * SP2 + 2.0 * SZ * SP + SZ2 * NN);
                g_count = 0;   // reset for next graph replay
            }
        }
    }
}

extern "C" void kernel_launch(void* const* d_in, const int* in_sizes, int n_in,
                              void* d_out, int out_size)
{
    const float* pred = (const float*)d_in[0];
    const int*   lab  = (const int*)d_in[1];
    float*       out  = (float*)d_out;
    const int n = in_sizes[0];

    sqloss_pf<<<NBLK, NTHR>>>(pred, lab, n, out);
}